// round 12
// baseline (speedup 1.0000x reference)
#include <cuda_runtime.h>
#include <cuda_bf16.h>
#include <math.h>
#include <stdint.h>

// Problem constants
#define Bq   8
#define Nn   8192
#define Hh   256
#define Ff   320
#define Ss   32
#define Mtot (Bq * Nn)      // 65536
#define NSPLIT 64

// Scratch (static device globals — no cudaMalloc allowed)
__device__ float g_xall[(size_t)Mtot * Hh];        // gated features [B*N, H]
__device__ float g_np[2 * Mtot];                   // partial norm^2 (nt 0/1)
__device__ float g_part[(size_t)NSPLIT * Bq * Ss * Hh];  // split-K partials
// combined weights [Wi;Wj] = 512 rows x 320 cols, bf16 hi/lo,
// tiled as [kchunk 10][n 512][k 32] for direct cp.async
__device__ __nv_bfloat16 g_wh[512 * Ff];
__device__ __nv_bfloat16 g_wl[512 * Ff];

// ======================= helpers ============================================
__device__ __forceinline__ uint32_t smem_u32(const void* p) {
    uint32_t a;
    asm("{ .reg .u64 t; cvta.to.shared.u64 t, %1; cvt.u32.u64 %0, t; }"
        : "=r"(a) : "l"(p));
    return a;
}
// SW64 swizzle for 64B rows: bits[5:4] ^= bits[8:7]
__device__ __forceinline__ uint32_t swz(uint32_t o) {
    return o ^ ((o >> 3) & 0x30);
}
__device__ __forceinline__ void cp16(uint32_t dst, const void* src) {
    asm volatile("cp.async.cg.shared.global [%0], [%1], 16;"
                 :: "r"(dst), "l"(src) : "memory");
}
#define CP_COMMIT() asm volatile("cp.async.commit_group;" ::: "memory")
#define CP_WAIT0()  asm volatile("cp.async.wait_group 0;" ::: "memory")

#define LDSM4(r, addr)                                                         \
    asm volatile("ldmatrix.sync.aligned.m8n8.x4.shared.b16 {%0,%1,%2,%3}, [%4];" \
                 : "=r"((r)[0]), "=r"((r)[1]), "=r"((r)[2]), "=r"((r)[3])      \
                 : "r"(addr))

__device__ __forceinline__ void mma16816(float* d, const uint32_t* a,
                                         uint32_t b0, uint32_t b1) {
    asm volatile(
        "mma.sync.aligned.m16n8k16.row.col.f32.bf16.bf16.f32 "
        "{%0,%1,%2,%3}, {%4,%5,%6,%7}, {%8,%9}, {%0,%1,%2,%3};"
        : "+f"(d[0]), "+f"(d[1]), "+f"(d[2]), "+f"(d[3])
        : "r"(a[0]), "r"(a[1]), "r"(a[2]), "r"(a[3]), "r"(b0), "r"(b1));
}

// packed f32x2 helpers
__device__ __forceinline__ unsigned long long pk2(float lo, float hi) {
    unsigned long long r;
    asm("mov.b64 %0, {%1, %2};" : "=l"(r) : "f"(lo), "f"(hi));
    return r;
}
__device__ __forceinline__ unsigned long long fma2(unsigned long long a,
                                                   unsigned long long b,
                                                   unsigned long long c) {
    unsigned long long d;
    asm("fma.rn.f32x2 %0, %1, %2, %3;" : "=l"(d) : "l"(a), "l"(b), "l"(c));
    return d;
}
__device__ __forceinline__ float2 upk2(unsigned long long v) {
    float lo, hi;
    asm("mov.b64 {%0, %1}, %2;" : "=f"(lo), "=f"(hi) : "l"(v));
    return make_float2(lo, hi);
}

__device__ __forceinline__ float gate_fn(float zi, float zj) {
    float s = 1.0f / (1.0f + expf(-zi));
    return s * tanhf(zj);
}

// SMEM map (dynamic):
//  2 stages of 49152B: A hi +0 (8KB), A lo +8192, B hi +16384 (16KB), B lo +32768
//  epilogue reuses [0,135168) as fp32 [128][264] (padded); bias at 135168 (256 f32)
#define STG     49152
#define SM_EXW  264
#define SM_BIAS 135168
#define SM_TOT  136192

// ============================================================================
// k_wconv: split+tile weights: g_wh/g_wl[(c*512+n)*32+kk], f = c*32+kk
// ============================================================================
__global__ __launch_bounds__(256) void k_wconv(const float* __restrict__ Wi,
                                               const float* __restrict__ Wj) {
    int i = blockIdx.x * 256 + threadIdx.x;   // 0..163839
    int c  = i >> 14;
    int r  = i & 16383;
    int n  = r >> 5;
    int kk = r & 31;
    int f  = c * 32 + kk;
    float v = (n < 256) ? Wi[n * Ff + f] : Wj[(n - 256) * Ff + f];
    __nv_bfloat16 h = __float2bfloat16(v);
    g_wh[i] = h;
    g_wl[i] = __float2bfloat16(v - __bfloat162float(h));
}

// ============================================================================
// k_gemm_mma: dual GEMM (bf16 split-2, 3 HMMA passes) + gate + partial L2
// norm. CTA: 128M x 256N (128 Di-cols + 128 Dj-cols at offset nt*128).
// 512 thr = 16 warps; warp (wm=wid>>1, wn=wid&1): tile 16m x 128n.
// MMA issue order: grouped passes, all accumulator reuse >= 8 issues apart.
// ============================================================================
__global__ __launch_bounds__(512, 1) void k_gemm_mma(
    const float* __restrict__ x,
    const float* __restrict__ bi, const float* __restrict__ bj)
{
    extern __shared__ __align__(128) char smem[];
    const uint32_t sb = smem_u32(smem);
    const int t    = threadIdx.x;
    const int lane = t & 31;
    const int wid  = t >> 5;
    const int wm   = wid >> 1;            // 0..7
    const int wn   = wid & 1;             // 0..1
    const int m0   = blockIdx.x * 128;
    const int nt   = blockIdx.y;          // 0/1: which 128-col slice of Di/Dj

    // bias preload for this CTA's 128 Di + 128 Dj cols
    float* biasS = (float*)(smem + SM_BIAS);
    if (t < 128)            biasS[t] = bi[nt * 128 + t];
    else if (t < 256)       biasS[t] = bj[nt * 128 + (t - 128)];

    float acc[16][4] = {};

    // A addressing: thread owns row t>>2, 8 floats at col (t&3)*8
    const int xrow = t >> 2, xc = t & 3;
    const float* xptr = x + (size_t)(m0 + xrow) * Ff + xc * 8;

    // ---- B issue into stage st for chunk it (256 rows x 64B, hi+lo)
    auto issueB = [&](int it, int st) {
        uint32_t bB = sb + st * STG + 16384;
#pragma unroll
        for (int i = 0; i < 2; i++) {
            int e    = t + i * 512;        // 0..1023
            int brow = e >> 2;             // 0..255
            int kc   = e & 3;
            int gn   = nt * 128 + brow + (brow & 128);  // global n in [0,512)
            uint32_t so = swz((uint32_t)brow * 64 + kc * 16);
            size_t s = (size_t)it * 16384 + (size_t)gn * 32 + kc * 8;
            cp16(bB + so,         g_wh + s);
            cp16(bB + 16384 + so, g_wl + s);
        }
    };
    // ---- A convert fp32 -> bf16 hi/lo (8 vals/thread), STS swizzled
    auto stsA = [&](float4 v0, float4 v1, int st) {
        float vv[8] = {v0.x, v0.y, v0.z, v0.w, v1.x, v1.y, v1.z, v1.w};
        uint32_t ph[4], pl[4];
#pragma unroll
        for (int q = 0; q < 4; q++) {
            __nv_bfloat16 h0 = __float2bfloat16(vv[2 * q]);
            __nv_bfloat16 h1 = __float2bfloat16(vv[2 * q + 1]);
            __nv_bfloat16 l0 = __float2bfloat16(vv[2 * q]     - __bfloat162float(h0));
            __nv_bfloat16 l1 = __float2bfloat16(vv[2 * q + 1] - __bfloat162float(h1));
            ph[q] = (uint32_t)__bfloat16_as_ushort(h0) |
                    ((uint32_t)__bfloat16_as_ushort(h1) << 16);
            pl[q] = (uint32_t)__bfloat16_as_ushort(l0) |
                    ((uint32_t)__bfloat16_as_ushort(l1) << 16);
        }
        uint32_t off = swz((uint32_t)xrow * 64 + xc * 16);
        *(uint4*)(smem + st * STG + off)        = make_uint4(ph[0], ph[1], ph[2], ph[3]);
        *(uint4*)(smem + st * STG + 8192 + off) = make_uint4(pl[0], pl[1], pl[2], pl[3]);
    };
    // ---- compute one k32 chunk from stage st.
    // Order per 4-bn group: pass1 ah*bh (x8), pass3 al*bh (x8, bh regs then
    // overwritten with bl), pass2 ah*bl (x8). Acc reuse distance >= 8 issues.
    auto compute = [&](int st) {
        uint32_t aB = sb + st * STG;
        uint32_t bB = aB + 16384;
        const uint32_t arow = wm * 16 + (lane & 7) + ((lane >> 3) & 1) * 8;
        const uint32_t c16  = (lane >> 4) & 1;
        const uint32_t brow = wn * 128 + (lane & 7) + ((lane >> 3) & 1) * 8;
#pragma unroll
        for (int k16 = 0; k16 < 2; k16++) {
            uint32_t ao = swz(arow * 64 + k16 * 32 + c16 * 16);
            uint32_t ah[4], al[4];
            LDSM4(ah, aB + ao);
            LDSM4(al, aB + 8192 + ao);
#pragma unroll
            for (int g = 0; g < 2; g++) {
                uint32_t b4[4][4];
                uint32_t bo[4];
#pragma unroll
                for (int q = 0; q < 4; q++) {
                    int bn = g * 4 + q;
                    bo[q] = swz((brow + bn * 16) * 64 + k16 * 32 + c16 * 16);
                    LDSM4(b4[q], bB + bo[q]);
                }
                // pass 1: ah * bh
#pragma unroll
                for (int q = 0; q < 4; q++) {
                    int bn = g * 4 + q;
                    mma16816(acc[bn * 2],     ah, b4[q][0], b4[q][2]);
                    mma16816(acc[bn * 2 + 1], ah, b4[q][1], b4[q][3]);
                }
                // pass 3: al * bh; after last read, overwrite cache with bl
#pragma unroll
                for (int q = 0; q < 4; q++) {
                    int bn = g * 4 + q;
                    mma16816(acc[bn * 2],     al, b4[q][0], b4[q][2]);
                    mma16816(acc[bn * 2 + 1], al, b4[q][1], b4[q][3]);
                    LDSM4(b4[q], bB + 16384 + bo[q]);
                }
                // pass 2: ah * bl
#pragma unroll
                for (int q = 0; q < 4; q++) {
                    int bn = g * 4 + q;
                    mma16816(acc[bn * 2],     ah, b4[q][0], b4[q][2]);
                    mma16816(acc[bn * 2 + 1], ah, b4[q][1], b4[q][3]);
                }
            }
        }
    };

    // ---- prologue: chunk 0 into buf 0
    stsA(*(const float4*)xptr, *(const float4*)(xptr + 4), 0);
    issueB(0, 0);
    CP_COMMIT();

    // ---- main loop: 10 chunks, double buffered
    for (int it = 0; it < 10; it++) {
        int buf = it & 1;
        CP_WAIT0();
        __syncthreads();
        float4 xn0, xn1;
        if (it < 9) {
            xn0 = *(const float4*)(xptr + (it + 1) * 32);
            xn1 = *(const float4*)(xptr + (it + 1) * 32 + 4);
            issueB(it + 1, buf ^ 1);
            CP_COMMIT();
        }
        compute(buf);
        if (it < 9) stsA(xn0, xn1, buf ^ 1);
    }
    __syncthreads();

    // ---- epilogue: exchange acc via smem fp32 [128][264] (padded stride)
    float* ex = (float*)smem;
#pragma unroll
    for (int fn = 0; fn < 16; fn++) {
        int col = wn * 128 + fn * 8 + (lane & 3) * 2;
        int row = wm * 16 + (lane >> 2);
        ex[row * SM_EXW + col]           = acc[fn][0];
        ex[row * SM_EXW + col + 1]       = acc[fn][1];
        ex[(row + 8) * SM_EXW + col]     = acc[fn][2];
        ex[(row + 8) * SM_EXW + col + 1] = acc[fn][3];
    }
    __syncthreads();

    // gate + write g_xall + partial norm. thread: row t>>2, 32 cols
    const int grow = t >> 2, gc = t & 3;
    float nrm = 0.0f;
#pragma unroll
    for (int j = 0; j < 8; j++) {
        int hl = gc * 4 + j * 16;     // local Di col 0..127
        float4 di = *(float4*)&ex[grow * SM_EXW + hl];
        float4 dj = *(float4*)&ex[grow * SM_EXW + 128 + hl];
        float4 bi4 = *(float4*)&biasS[hl];
        float4 bj4 = *(float4*)&biasS[128 + hl];
        float4 o;
        o.x = gate_fn(di.x + bi4.x, dj.x + bj4.x);
        o.y = gate_fn(di.y + bi4.y, dj.y + bj4.y);
        o.z = gate_fn(di.z + bi4.z, dj.z + bj4.z);
        o.w = gate_fn(di.w + bi4.w, dj.w + bj4.w);
        nrm += o.x * o.x + o.y * o.y + o.z * o.z + o.w * o.w;
        *(float4*)&g_xall[(size_t)(m0 + grow) * Hh + nt * 128 + hl] = o;
    }
    nrm += __shfl_xor_sync(0xFFFFFFFFu, nrm, 1);
    nrm += __shfl_xor_sync(0xFFFFFFFFu, nrm, 2);
    if ((lane & 3) == 0) g_np[(size_t)nt * Mtot + m0 + grow] = nrm;
}

// ============================================================================
// k_weight: masked softmax over nodes. One block per (b,s).
// norm = sqrt(p0 + p1) from the two GEMM partials.
// ============================================================================
__global__ __launch_bounds__(256) void k_weight(const float* __restrict__ node_map,
                                                float* __restrict__ wout) {
    __shared__ float e[Nn];
    __shared__ float red[256];
    int bs = blockIdx.x;
    int b  = bs >> 5;
    const float* nm  = node_map + (size_t)bs * Nn;
    const float* np0 = g_np + (size_t)b * Nn;
    const float* np1 = g_np + (size_t)Mtot + (size_t)b * Nn;
    int t = threadIdx.x;
    float part = 0.0f;
    for (int n = t; n < Nn; n += 256) {
        float v  = nm[n] * sqrtf(np0[n] + np1[n]);
        float ev = (v > 0.0f) ? expf(v) : 0.0f;
        e[n] = ev;
        part += ev;
    }
    red[t] = part;
    __syncthreads();
#pragma unroll
    for (int o = 128; o > 0; o >>= 1) {
        if (t < o) red[t] += red[t + o];
        __syncthreads();
    }
    float sum = red[0];
    float inv = (sum > 0.0f) ? (1.0f / sum) : 0.0f;
    float* wrow = wout + (size_t)bs * Nn;
    for (int n = t; n < Nn; n += 256) wrow[n] = e[n] * inv;
}

// ============================================================================
// k_pool: split-K pooled partials, full-H blocks, FFMA2.
// ============================================================================
__global__ __launch_bounds__(256) void k_pool(const float* __restrict__ w) {
    __shared__ float xs[32][256];   // 32 KB
    __shared__ float ws[32][32];    //  4 KB
    const int chunk = blockIdx.x;
    const int b     = blockIdx.z;
    const int t     = threadIdx.x;
    const int h1 = (t & 31) * 4;
    const int sq = (t >> 5) * 4;
    const int nbase = chunk * (Nn / NSPLIT);

    unsigned long long acc2[4][4];
    const unsigned long long zz = pk2(0.0f, 0.0f);
#pragma unroll
    for (int i = 0; i < 4; i++)
#pragma unroll
        for (int j = 0; j < 4; j++) acc2[i][j] = zz;

    for (int n0 = 0; n0 < Nn / NSPLIT; n0 += 32) {
        __syncthreads();
#pragma unroll
        for (int i = 0; i < 8; i++) {
            int e  = t + i * 256;
            int nn = e >> 6;
            int hh = (e & 63) * 4;
            *(float4*)&xs[nn][hh] =
                *(const float4*)&g_xall[(size_t)(b * Nn + nbase + n0 + nn) * Hh + hh];
        }
        {
            int s  = t >> 3;
            int nn = (t & 7) * 4;
            float4 wv = *(const float4*)&w[(size_t)(b * Ss + s) * Nn + nbase + n0 + nn];
            ws[nn + 0][s] = wv.x; ws[nn + 1][s] = wv.y;
            ws[nn + 2][s] = wv.z; ws[nn + 3][s] = wv.w;
        }
        __syncthreads();
#pragma unroll
        for (int nc = 0; nc < 32; nc++) {
            ulonglong2 xa = *(const ulonglong2*)&xs[nc][h1];
            ulonglong2 xb = *(const ulonglong2*)&xs[nc][128 + h1];
            float4 wv = *(const float4*)&ws[nc][sq];
            unsigned long long wp[4];
            wp[0] = pk2(wv.x, wv.x); wp[1] = pk2(wv.y, wv.y);
            wp[2] = pk2(wv.z, wv.z); wp[3] = pk2(wv.w, wv.w);
#pragma unroll
            for (int i = 0; i < 4; i++) {
                acc2[i][0] = fma2(wp[i], xa.x, acc2[i][0]);
                acc2[i][1] = fma2(wp[i], xa.y, acc2[i][1]);
                acc2[i][2] = fma2(wp[i], xb.x, acc2[i][2]);
                acc2[i][3] = fma2(wp[i], xb.y, acc2[i][3]);
            }
        }
    }
#pragma unroll
    for (int i = 0; i < 4; i++) {
        float2 a0 = upk2(acc2[i][0]), a1 = upk2(acc2[i][1]);
        float2 b0 = upk2(acc2[i][2]), b1 = upk2(acc2[i][3]);
        size_t base = (size_t)((chunk * Bq + b) * Ss + sq + i) * Hh;
        *(float4*)&g_part[base + h1]       = make_float4(a0.x, a0.y, a1.x, a1.y);
        *(float4*)&g_part[base + 128 + h1] = make_float4(b0.x, b0.y, b1.x, b1.y);
    }
}

// ============================================================================
// k_final: deterministic split-K reduce + tanh
// ============================================================================
__global__ __launch_bounds__(256) void k_final(float* __restrict__ out) {
    int g = blockIdx.x * blockDim.x + threadIdx.x;
    float s = 0.0f;
#pragma unroll
    for (int c = 0; c < NSPLIT; c++) s += g_part[(size_t)c * (Bq * Ss * Hh) + g];
    out[g] = tanhf(s);
}

// ============================================================================
extern "C" void kernel_launch(void* const* d_in, const int* in_sizes, int n_in,
                              void* d_out, int out_size) {
    const float* x        = (const float*)d_in[0];
    const float* node_map = (const float*)d_in[1];
    const float* Wi       = (const float*)d_in[2];
    const float* bi       = (const float*)d_in[3];
    const float* Wj       = (const float*)d_in[4];
    const float* bj       = (const float*)d_in[5];
    float* out  = (float*)d_out;
    float* wout = out + (size_t)Bq * Ss * Hh;

    cudaFuncSetAttribute(k_gemm_mma, cudaFuncAttributeMaxDynamicSharedMemorySize, SM_TOT);

    k_wconv<<<(512 * Ff) / 256, 256>>>(Wi, Wj);
    k_gemm_mma<<<dim3(Mtot / 128, 2), 512, SM_TOT>>>(x, bi, bj);
    k_weight<<<Bq * Ss, 256>>>(node_map, wout);
    k_pool<<<dim3(NSPLIT, 1, Bq), 256>>>(wout);
    k_final<<<(Bq * Ss * Hh) / 256, 256>>>(out);
}

// round 13
// speedup vs baseline: 1.5960x; 1.5960x over previous
#include <cuda_runtime.h>
#include <cuda_fp16.h>
#include <math.h>
#include <stdint.h>

// Problem constants
#define Bq   8
#define Nn   8192
#define Hh   256
#define Ff   320
#define Ss   32
#define Mtot (Bq * Nn)      // 65536
#define NSPLIT 64

// Scratch (static device globals — no cudaMalloc allowed)
__device__ float g_xall[(size_t)Mtot * Hh];        // gated features [B*N, H]
__device__ float g_np[2 * Mtot];                   // partial norm^2 (nt 0/1)
__device__ float g_part[(size_t)NSPLIT * Bq * Ss * Hh];  // split-K partials
// combined weights [Wi;Wj] = 512 rows x 320 cols, fp16,
// tiled as [kchunk 10][n 512][k 32] for direct cp.async
__device__ __half g_w[512 * Ff];

// ======================= helpers ============================================
__device__ __forceinline__ uint32_t smem_u32(const void* p) {
    uint32_t a;
    asm("{ .reg .u64 t; cvta.to.shared.u64 t, %1; cvt.u32.u64 %0, t; }"
        : "=r"(a) : "l"(p));
    return a;
}
// SW64 swizzle for 64B rows: bits[5:4] ^= bits[8:7]
__device__ __forceinline__ uint32_t swz(uint32_t o) {
    return o ^ ((o >> 3) & 0x30);
}
__device__ __forceinline__ void cp16(uint32_t dst, const void* src) {
    asm volatile("cp.async.cg.shared.global [%0], [%1], 16;"
                 :: "r"(dst), "l"(src) : "memory");
}
#define CP_COMMIT() asm volatile("cp.async.commit_group;" ::: "memory")
#define CP_WAIT0()  asm volatile("cp.async.wait_group 0;" ::: "memory")

#define LDSM4(r, addr)                                                         \
    asm volatile("ldmatrix.sync.aligned.m8n8.x4.shared.b16 {%0,%1,%2,%3}, [%4];" \
                 : "=r"((r)[0]), "=r"((r)[1]), "=r"((r)[2]), "=r"((r)[3])      \
                 : "r"(addr))

__device__ __forceinline__ void mma16816h(float* d, const uint32_t* a,
                                          uint32_t b0, uint32_t b1) {
    asm volatile(
        "mma.sync.aligned.m16n8k16.row.col.f32.f16.f16.f32 "
        "{%0,%1,%2,%3}, {%4,%5,%6,%7}, {%8,%9}, {%0,%1,%2,%3};"
        : "+f"(d[0]), "+f"(d[1]), "+f"(d[2]), "+f"(d[3])
        : "r"(a[0]), "r"(a[1]), "r"(a[2]), "r"(a[3]), "r"(b0), "r"(b1));
}

// packed f32x2 helpers (k_pool)
__device__ __forceinline__ unsigned long long pk2(float lo, float hi) {
    unsigned long long r;
    asm("mov.b64 %0, {%1, %2};" : "=l"(r) : "f"(lo), "f"(hi));
    return r;
}
__device__ __forceinline__ unsigned long long fma2(unsigned long long a,
                                                   unsigned long long b,
                                                   unsigned long long c) {
    unsigned long long d;
    asm("fma.rn.f32x2 %0, %1, %2, %3;" : "=l"(d) : "l"(a), "l"(b), "l"(c));
    return d;
}
__device__ __forceinline__ float2 upk2(unsigned long long v) {
    float lo, hi;
    asm("mov.b64 {%0, %1}, %2;" : "=f"(lo), "=f"(hi) : "l"(v));
    return make_float2(lo, hi);
}

__device__ __forceinline__ float gate_fn(float zi, float zj) {
    float s = 1.0f / (1.0f + expf(-zi));
    return s * tanhf(zj);
}

// SMEM map (dynamic):
//  2 stages of 24576B: A fp16 +0 (8KB, 128 rows x 64B), B fp16 +8192 (16KB)
//  epilogue reuses [0,135168) as fp32 [128][264] (padded); bias at 135168
#define STG     24576
#define SM_EXW  264
#define SM_BIAS 135168
#define SM_TOT  136192

// ============================================================================
// k_wconv: convert+tile weights: g_w[(c*512+n)*32+kk], f = c*32+kk
// ============================================================================
__global__ __launch_bounds__(256) void k_wconv(const float* __restrict__ Wi,
                                               const float* __restrict__ Wj) {
    int i = blockIdx.x * 256 + threadIdx.x;   // 0..163839
    int c  = i >> 14;
    int r  = i & 16383;
    int n  = r >> 5;
    int kk = r & 31;
    int f  = c * 32 + kk;
    float v = (n < 256) ? Wi[n * Ff + f] : Wj[(n - 256) * Ff + f];
    g_w[i] = __float2half_rn(v);
}

// ============================================================================
// k_gemm_mma: dual GEMM (single-pass fp16 HMMA) + gate + partial L2 norm.
// CTA: 128M x 256N (128 Di-cols + 128 Dj-cols at offset nt*128).
// 512 thr = 16 warps; warp (wm=wid>>1, wn=wid&1): tile 16m x 128n.
// Double-buffered cp.async (R11-proven structure).
// ============================================================================
__global__ __launch_bounds__(512, 1) void k_gemm_mma(
    const float* __restrict__ x,
    const float* __restrict__ bi, const float* __restrict__ bj)
{
    extern __shared__ __align__(128) char smem[];
    const uint32_t sb = smem_u32(smem);
    const int t    = threadIdx.x;
    const int lane = t & 31;
    const int wid  = t >> 5;
    const int wm   = wid >> 1;            // 0..7
    const int wn   = wid & 1;             // 0..1
    const int m0   = blockIdx.x * 128;
    const int nt   = blockIdx.y;          // 0/1: which 128-col slice of Di/Dj

    // bias preload for this CTA's 128 Di + 128 Dj cols
    float* biasS = (float*)(smem + SM_BIAS);
    if (t < 128)            biasS[t] = bi[nt * 128 + t];
    else if (t < 256)       biasS[t] = bj[nt * 128 + (t - 128)];

    float acc[16][4] = {};

    // A addressing: thread owns row t>>2, 8 floats at col (t&3)*8
    const int xrow = t >> 2, xc = t & 3;
    const float* xptr = x + (size_t)(m0 + xrow) * Ff + xc * 8;

    // ---- B issue into stage st for chunk it (256 rows x 64B fp16)
    auto issueB = [&](int it, int st) {
        uint32_t bB = sb + st * STG + 8192;
#pragma unroll
        for (int i = 0; i < 2; i++) {
            int e    = t + i * 512;        // 0..1023
            int brow = e >> 2;             // 0..255
            int kc   = e & 3;
            int gn   = nt * 128 + brow + (brow & 128);  // global n in [0,512)
            uint32_t so = swz((uint32_t)brow * 64 + kc * 16);
            cp16(bB + so, g_w + (size_t)it * 16384 + (size_t)gn * 32 + kc * 8);
        }
    };
    // ---- A convert fp32 -> fp16 (8 vals/thread), STS swizzled
    auto stsA = [&](float4 v0, float4 v1, int st) {
        __half2 h0 = __floats2half2_rn(v0.x, v0.y);
        __half2 h1 = __floats2half2_rn(v0.z, v0.w);
        __half2 h2 = __floats2half2_rn(v1.x, v1.y);
        __half2 h3 = __floats2half2_rn(v1.z, v1.w);
        uint4 pv = make_uint4(*(uint32_t*)&h0, *(uint32_t*)&h1,
                              *(uint32_t*)&h2, *(uint32_t*)&h3);
        uint32_t off = swz((uint32_t)xrow * 64 + xc * 16);
        *(uint4*)(smem + st * STG + off) = pv;
    };
    // ---- compute one k32 chunk from stage st
    auto compute = [&](int st) {
        uint32_t aB = sb + st * STG;
        uint32_t bB = aB + 8192;
        const uint32_t arow = wm * 16 + (lane & 7) + ((lane >> 3) & 1) * 8;
        const uint32_t c16  = (lane >> 4) & 1;
        const uint32_t brow = wn * 128 + (lane & 7) + ((lane >> 3) & 1) * 8;
#pragma unroll
        for (int k16 = 0; k16 < 2; k16++) {
            uint32_t ao = swz(arow * 64 + k16 * 32 + c16 * 16);
            uint32_t a4[4];
            LDSM4(a4, aB + ao);
#pragma unroll
            for (int bn = 0; bn < 8; bn++) {
                uint32_t bo = swz((brow + bn * 16) * 64 + k16 * 32 + c16 * 16);
                uint32_t b4[4];
                LDSM4(b4, bB + bo);
                mma16816h(acc[bn * 2],     a4, b4[0], b4[2]);
                mma16816h(acc[bn * 2 + 1], a4, b4[1], b4[3]);
            }
        }
    };

    // ---- prologue: chunk 0 into buf 0
    stsA(*(const float4*)xptr, *(const float4*)(xptr + 4), 0);
    issueB(0, 0);
    CP_COMMIT();

    // ---- main loop: 10 chunks, double buffered
    for (int it = 0; it < 10; it++) {
        int buf = it & 1;
        CP_WAIT0();
        __syncthreads();
        float4 xn0, xn1;
        if (it < 9) {
            xn0 = *(const float4*)(xptr + (it + 1) * 32);
            xn1 = *(const float4*)(xptr + (it + 1) * 32 + 4);
            issueB(it + 1, buf ^ 1);
            CP_COMMIT();
        }
        compute(buf);
        if (it < 9) stsA(xn0, xn1, buf ^ 1);
    }
    __syncthreads();

    // ---- epilogue: exchange acc via smem fp32 [128][264] (padded stride)
    float* ex = (float*)smem;
#pragma unroll
    for (int fn = 0; fn < 16; fn++) {
        int col = wn * 128 + fn * 8 + (lane & 3) * 2;
        int row = wm * 16 + (lane >> 2);
        ex[row * SM_EXW + col]           = acc[fn][0];
        ex[row * SM_EXW + col + 1]       = acc[fn][1];
        ex[(row + 8) * SM_EXW + col]     = acc[fn][2];
        ex[(row + 8) * SM_EXW + col + 1] = acc[fn][3];
    }
    __syncthreads();

    // gate + write g_xall + partial norm. thread: row t>>2, 32 cols
    const int grow = t >> 2, gc = t & 3;
    float nrm = 0.0f;
#pragma unroll
    for (int j = 0; j < 8; j++) {
        int hl = gc * 4 + j * 16;     // local Di col 0..127
        float4 di = *(float4*)&ex[grow * SM_EXW + hl];
        float4 dj = *(float4*)&ex[grow * SM_EXW + 128 + hl];
        float4 bi4 = *(float4*)&biasS[hl];
        float4 bj4 = *(float4*)&biasS[128 + hl];
        float4 o;
        o.x = gate_fn(di.x + bi4.x, dj.x + bj4.x);
        o.y = gate_fn(di.y + bi4.y, dj.y + bj4.y);
        o.z = gate_fn(di.z + bi4.z, dj.z + bj4.z);
        o.w = gate_fn(di.w + bi4.w, dj.w + bj4.w);
        nrm += o.x * o.x + o.y * o.y + o.z * o.z + o.w * o.w;
        *(float4*)&g_xall[(size_t)(m0 + grow) * Hh + nt * 128 + hl] = o;
    }
    nrm += __shfl_xor_sync(0xFFFFFFFFu, nrm, 1);
    nrm += __shfl_xor_sync(0xFFFFFFFFu, nrm, 2);
    if ((lane & 3) == 0) g_np[(size_t)nt * Mtot + m0 + grow] = nrm;
}

// ============================================================================
// k_weight: masked softmax over nodes. One block per (b,s).
// norm = sqrt(p0 + p1) from the two GEMM partials.
// ============================================================================
__global__ __launch_bounds__(256) void k_weight(const float* __restrict__ node_map,
                                                float* __restrict__ wout) {
    __shared__ float e[Nn];
    __shared__ float red[256];
    int bs = blockIdx.x;
    int b  = bs >> 5;
    const float* nm  = node_map + (size_t)bs * Nn;
    const float* np0 = g_np + (size_t)b * Nn;
    const float* np1 = g_np + (size_t)Mtot + (size_t)b * Nn;
    int t = threadIdx.x;
    float part = 0.0f;
    for (int n = t; n < Nn; n += 256) {
        float v  = nm[n] * sqrtf(np0[n] + np1[n]);
        float ev = (v > 0.0f) ? expf(v) : 0.0f;
        e[n] = ev;
        part += ev;
    }
    red[t] = part;
    __syncthreads();
#pragma unroll
    for (int o = 128; o > 0; o >>= 1) {
        if (t < o) red[t] += red[t + o];
        __syncthreads();
    }
    float sum = red[0];
    float inv = (sum > 0.0f) ? (1.0f / sum) : 0.0f;
    float* wrow = wout + (size_t)bs * Nn;
    for (int n = t; n < Nn; n += 256) wrow[n] = e[n] * inv;
}

// ============================================================================
// k_pool: split-K pooled partials, full-H blocks, FFMA2.
// ============================================================================
__global__ __launch_bounds__(256) void k_pool(const float* __restrict__ w) {
    __shared__ float xs[32][256];   // 32 KB
    __shared__ float ws[32][32];    //  4 KB
    const int chunk = blockIdx.x;
    const int b     = blockIdx.z;
    const int t     = threadIdx.x;
    const int h1 = (t & 31) * 4;
    const int sq = (t >> 5) * 4;
    const int nbase = chunk * (Nn / NSPLIT);

    unsigned long long acc2[4][4];
    const unsigned long long zz = pk2(0.0f, 0.0f);
#pragma unroll
    for (int i = 0; i < 4; i++)
#pragma unroll
        for (int j = 0; j < 4; j++) acc2[i][j] = zz;

    for (int n0 = 0; n0 < Nn / NSPLIT; n0 += 32) {
        __syncthreads();
#pragma unroll
        for (int i = 0; i < 8; i++) {
            int e  = t + i * 256;
            int nn = e >> 6;
            int hh = (e & 63) * 4;
            *(float4*)&xs[nn][hh] =
                *(const float4*)&g_xall[(size_t)(b * Nn + nbase + n0 + nn) * Hh + hh];
        }
        {
            int s  = t >> 3;
            int nn = (t & 7) * 4;
            float4 wv = *(const float4*)&w[(size_t)(b * Ss + s) * Nn + nbase + n0 + nn];
            ws[nn + 0][s] = wv.x; ws[nn + 1][s] = wv.y;
            ws[nn + 2][s] = wv.z; ws[nn + 3][s] = wv.w;
        }
        __syncthreads();
#pragma unroll
        for (int nc = 0; nc < 32; nc++) {
            ulonglong2 xa = *(const ulonglong2*)&xs[nc][h1];
            ulonglong2 xb = *(const ulonglong2*)&xs[nc][128 + h1];
            float4 wv = *(const float4*)&ws[nc][sq];
            unsigned long long wp[4];
            wp[0] = pk2(wv.x, wv.x); wp[1] = pk2(wv.y, wv.y);
            wp[2] = pk2(wv.z, wv.z); wp[3] = pk2(wv.w, wv.w);
#pragma unroll
            for (int i = 0; i < 4; i++) {
                acc2[i][0] = fma2(wp[i], xa.x, acc2[i][0]);
                acc2[i][1] = fma2(wp[i], xa.y, acc2[i][1]);
                acc2[i][2] = fma2(wp[i], xb.x, acc2[i][2]);
                acc2[i][3] = fma2(wp[i], xb.y, acc2[i][3]);
            }
        }
    }
#pragma unroll
    for (int i = 0; i < 4; i++) {
        float2 a0 = upk2(acc2[i][0]), a1 = upk2(acc2[i][1]);
        float2 b0 = upk2(acc2[i][2]), b1 = upk2(acc2[i][3]);
        size_t base = (size_t)((chunk * Bq + b) * Ss + sq + i) * Hh;
        *(float4*)&g_part[base + h1]       = make_float4(a0.x, a0.y, a1.x, a1.y);
        *(float4*)&g_part[base + 128 + h1] = make_float4(b0.x, b0.y, b1.x, b1.y);
    }
}

// ============================================================================
// k_final: deterministic split-K reduce + tanh
// ============================================================================
__global__ __launch_bounds__(256) void k_final(float* __restrict__ out) {
    int g = blockIdx.x * blockDim.x + threadIdx.x;
    float s = 0.0f;
#pragma unroll
    for (int c = 0; c < NSPLIT; c++) s += g_part[(size_t)c * (Bq * Ss * Hh) + g];
    out[g] = tanhf(s);
}

// ============================================================================
extern "C" void kernel_launch(void* const* d_in, const int* in_sizes, int n_in,
                              void* d_out, int out_size) {
    const float* x        = (const float*)d_in[0];
    const float* node_map = (const float*)d_in[1];
    const float* Wi       = (const float*)d_in[2];
    const float* bi       = (const float*)d_in[3];
    const float* Wj       = (const float*)d_in[4];
    const float* bj       = (const float*)d_in[5];
    float* out  = (float*)d_out;
    float* wout = out + (size_t)Bq * Ss * Hh;

    cudaFuncSetAttribute(k_gemm_mma, cudaFuncAttributeMaxDynamicSharedMemorySize, SM_TOT);

    k_wconv<<<(512 * Ff) / 256, 256>>>(Wi, Wj);
    k_gemm_mma<<<dim3(Mtot / 128, 2), 512, SM_TOT>>>(x, bi, bj);
    k_weight<<<Bq * Ss, 256>>>(node_map, wout);
    k_pool<<<dim3(NSPLIT, 1, Bq), 256>>>(wout);
    k_final<<<(Bq * Ss * Hh) / 256, 256>>>(out);
}